// round 6
// baseline (speedup 1.0000x reference)
#include <cuda_runtime.h>

#define B_ 4
#define S_ 2048
#define E_ 1024
#define A_ 128
#define M_ (B_*S_)   // 8192

// scratch (device globals: no allocation allowed)
__device__ float g_q [M_*A_];        // [b][s][a], pre-scaled by 1/sqrt(A)
__device__ float g_kt[B_*A_*S_];     // [b][a][s]  (K transposed)
__device__ float g_v [M_*A_];        // [b][s][a]

// ---------------------------------------------------------------------------
// Projection: y[m][n] = sum_e x[m][e] * W[n][e]
// grid (128, 3): 3 -> which of K/Q/V. block 256 = 32c x 8r, micro 8 rows x 4 cols
// col mapping n = c + 32*j  (odd smem pitch 33 -> conflict-free B reads)
// ---------------------------------------------------------------------------
#define KT 32

__global__ __launch_bounds__(256) void proj_kernel(
    const float* __restrict__ x,
    const float* __restrict__ Wk,
    const float* __restrict__ Wq,
    const float* __restrict__ Wv)
{
    const int which = blockIdx.y;               // 0=K, 1=Q, 2=V
    const float* __restrict__ W = (which == 0) ? Wk : ((which == 1) ? Wq : Wv);
    const int m0  = blockIdx.x * 64;
    const int tid = threadIdx.x;
    const int c   = tid & 31;
    const int r   = tid >> 5;

    __shared__ float xs[64 * 33];
    __shared__ float ws[128 * 33];

    float acc[8][4];
#pragma unroll
    for (int i = 0; i < 8; i++)
#pragma unroll
        for (int j = 0; j < 4; j++) acc[i][j] = 0.f;

    const int xrow = tid >> 2;            // 0..63
    const int xcb  = (tid & 3) * 8;       // 0,8,16,24
    const int wrow = tid >> 1;            // 0..127
    const int wcb  = (tid & 1) * 16;      // 0,16

    for (int kt = 0; kt < E_; kt += KT) {
        // stage gmem -> regs
        float4 xa = *(const float4*)&x[(m0 + xrow) * E_ + kt + xcb];
        float4 xb = *(const float4*)&x[(m0 + xrow) * E_ + kt + xcb + 4];
        float4 w0 = *(const float4*)&W[wrow * E_ + kt + wcb];
        float4 w1 = *(const float4*)&W[wrow * E_ + kt + wcb + 4];
        float4 w2 = *(const float4*)&W[wrow * E_ + kt + wcb + 8];
        float4 w3 = *(const float4*)&W[wrow * E_ + kt + wcb + 12];

        __syncthreads();   // previous compute done
        {
            float* px = &xs[xrow * 33 + xcb];
            px[0]=xa.x; px[1]=xa.y; px[2]=xa.z; px[3]=xa.w;
            px[4]=xb.x; px[5]=xb.y; px[6]=xb.z; px[7]=xb.w;
            float* pw = &ws[wrow * 33 + wcb];
            pw[0]=w0.x; pw[1]=w0.y; pw[2]=w0.z; pw[3]=w0.w;
            pw[4]=w1.x; pw[5]=w1.y; pw[6]=w1.z; pw[7]=w1.w;
            pw[8]=w2.x; pw[9]=w2.y; pw[10]=w2.z; pw[11]=w2.w;
            pw[12]=w3.x; pw[13]=w3.y; pw[14]=w3.z; pw[15]=w3.w;
        }
        __syncthreads();   // smem ready

#pragma unroll 4
        for (int kk = 0; kk < KT; kk++) {
            float a[8];
#pragma unroll
            for (int i = 0; i < 8; i++) a[i] = xs[(r * 8 + i) * 33 + kk];
            float b0 = ws[(c      ) * 33 + kk];
            float b1 = ws[(c + 32 ) * 33 + kk];
            float b2 = ws[(c + 64 ) * 33 + kk];
            float b3 = ws[(c + 96 ) * 33 + kk];
#pragma unroll
            for (int i = 0; i < 8; i++) {
                acc[i][0] += a[i] * b0;
                acc[i][1] += a[i] * b1;
                acc[i][2] += a[i] * b2;
                acc[i][3] += a[i] * b3;
            }
        }
    }

    const float qscale = 0.08838834764831843f;  // 1/sqrt(128)
#pragma unroll
    for (int i = 0; i < 8; i++) {
        const int m = m0 + r * 8 + i;
#pragma unroll
        for (int j = 0; j < 4; j++) {
            const int n = c + 32 * j;
            float v = acc[i][j];
            if (which == 1) {
                g_q[m * A_ + n] = v * qscale;
            } else if (which == 2) {
                g_v[m * A_ + n] = v;
            } else {
                const int bb = m >> 11;          // /2048
                const int s  = m & (S_ - 1);
                g_kt[(bb * A_ + n) * S_ + s] = v;
            }
        }
    }
}

// ---------------------------------------------------------------------------
// Flash attention (causal), fp32.
// grid (32 q-tiles, 4 batches). block 256 = 32c x 8r.
// BM=64 queries, BN=128 keys/iter, D=128.
// ---------------------------------------------------------------------------
#define BM 64
#define BN 128
#define QP 132   // smem pitch (floats), 16B-aligned rows

#define ATTN_SMEM ((64 + 128 + 128 + 64) * QP * 4)

__global__ __launch_bounds__(256, 1) void attn_kernel(float* __restrict__ out)
{
    extern __shared__ float sm[];
    float* q_s = sm;                    // [64][QP]   q_s[row][d]
    float* k_s = q_s + 64  * QP;        // [128][QP]  k_s[d][key]
    float* v_s = k_s + 128 * QP;        // [128][QP]  v_s[key][d]
    float* p_s = v_s + 128 * QP;        // [64][QP]   p_s[row][key]

    const int qt  = blockIdx.x;         // 0..31
    const int b   = blockIdx.y;         // 0..3
    const int q0  = qt * BM;
    const int tid = threadIdx.x;
    const int c   = tid & 31;
    const int r   = tid >> 5;

    // load Q tile (pre-scaled)
    {
        const int row = tid >> 2;              // 0..63
        const int cb  = (tid & 3) * 32;
        const float* gq = &g_q[(b * S_ + q0 + row) * A_ + cb];
        float* dq = &q_s[row * QP + cb];
#pragma unroll
        for (int u = 0; u < 8; u++)
            *(float4*)(dq + u * 4) = *(const float4*)(gq + u * 4);
    }

    float m_i[8], l_i[8], o[8][4];
#pragma unroll
    for (int i = 0; i < 8; i++) {
        m_i[i] = -1e30f; l_i[i] = 0.f;
#pragma unroll
        for (int j = 0; j < 4; j++) o[i][j] = 0.f;
    }

    const int hrow = tid >> 1;                 // 0..127
    const int hcb  = (tid & 1) * 64;           // 0,64
    const int ntiles = (q0 + BM + BN - 1) / BN;

    for (int t = 0; t < ntiles; t++) {
        const int kb = t * BN;

        __syncthreads();   // Q ready (t=0) / prev PV done
        {
            const float* gk = &g_kt[(b * A_ + hrow) * S_ + kb + hcb];
            float* dk = &k_s[hrow * QP + hcb];
#pragma unroll
            for (int u = 0; u < 16; u++)
                *(float4*)(dk + u * 4) = *(const float4*)(gk + u * 4);
            const float* gv = &g_v[(b * S_ + kb + hrow) * A_ + hcb];
            float* dv = &v_s[hrow * QP + hcb];
#pragma unroll
            for (int u = 0; u < 16; u++)
                *(float4*)(dv + u * 4) = *(const float4*)(gv + u * 4);
        }
        __syncthreads();

        // S = Q K^T (Q already scaled)
        float sacc[8][4];
#pragma unroll
        for (int i = 0; i < 8; i++)
#pragma unroll
            for (int j = 0; j < 4; j++) sacc[i][j] = 0.f;

#pragma unroll 4
        for (int kk = 0; kk < 128; kk++) {
            float a[8];
#pragma unroll
            for (int i = 0; i < 8; i++) a[i] = q_s[(r * 8 + i) * QP + kk];
            float4 bb = *(const float4*)&k_s[kk * QP + c * 4];
#pragma unroll
            for (int i = 0; i < 8; i++) {
                sacc[i][0] += a[i] * bb.x;
                sacc[i][1] += a[i] * bb.y;
                sacc[i][2] += a[i] * bb.z;
                sacc[i][3] += a[i] * bb.w;
            }
        }

        // causal mask (only needed on the diagonal tile)
        if (kb + BN - 1 > q0) {
#pragma unroll
            for (int i = 0; i < 8; i++) {
                const int qg = q0 + r * 8 + i;
#pragma unroll
                for (int j = 0; j < 4; j++) {
                    const int kj = kb + c * 4 + j;
                    if (kj > qg) sacc[i][j] = -1e30f;
                }
            }
        }

        // online softmax
#pragma unroll
        for (int i = 0; i < 8; i++) {
            float mx = fmaxf(fmaxf(sacc[i][0], sacc[i][1]),
                             fmaxf(sacc[i][2], sacc[i][3]));
#pragma unroll
            for (int off = 16; off > 0; off >>= 1)
                mx = fmaxf(mx, __shfl_xor_sync(0xffffffffu, mx, off));
            const float mnew  = fmaxf(m_i[i], mx);
            const float alpha = __expf(m_i[i] - mnew);
            float4 p;
            p.x = __expf(sacc[i][0] - mnew);
            p.y = __expf(sacc[i][1] - mnew);
            p.z = __expf(sacc[i][2] - mnew);
            p.w = __expf(sacc[i][3] - mnew);
            float ss = (p.x + p.y) + (p.z + p.w);
#pragma unroll
            for (int off = 16; off > 0; off >>= 1)
                ss += __shfl_xor_sync(0xffffffffu, ss, off);
            l_i[i] = l_i[i] * alpha + ss;
            m_i[i] = mnew;
            *(float4*)&p_s[(r * 8 + i) * QP + c * 4] = p;
#pragma unroll
            for (int j = 0; j < 4; j++) o[i][j] *= alpha;
        }
        __syncwarp();   // p_s rows are warp-private

        // O += P V
#pragma unroll 4
        for (int jj = 0; jj < 128; jj++) {
            float pp[8];
#pragma unroll
            for (int i = 0; i < 8; i++) pp[i] = p_s[(r * 8 + i) * QP + jj];
            float4 vv = *(const float4*)&v_s[jj * QP + c * 4];
#pragma unroll
            for (int i = 0; i < 8; i++) {
                o[i][0] += pp[i] * vv.x;
                o[i][1] += pp[i] * vv.y;
                o[i][2] += pp[i] * vv.z;
                o[i][3] += pp[i] * vv.w;
            }
        }
    }

    // epilogue
#pragma unroll
    for (int i = 0; i < 8; i++) {
        const float inv = 1.f / l_i[i];
        float4 res;
        res.x = o[i][0] * inv;
        res.y = o[i][1] * inv;
        res.z = o[i][2] * inv;
        res.w = o[i][3] * inv;
        *(float4*)&out[(b * S_ + q0 + r * 8 + i) * A_ + c * 4] = res;
    }
}

// ---------------------------------------------------------------------------
extern "C" void kernel_launch(void* const* d_in, const int* in_sizes, int n_in,
                              void* d_out, int out_size)
{
    const float* x  = (const float*)d_in[0];   // embedded [4,2048,1024]
    const float* Wk = (const float*)d_in[1];   // [128,1024]
    const float* Wq = (const float*)d_in[2];
    const float* Wv = (const float*)d_in[3];
    float* out = (float*)d_out;                // [4,2048,128] fp32

    cudaFuncSetAttribute(attn_kernel,
                         cudaFuncAttributeMaxDynamicSharedMemorySize,
                         ATTN_SMEM);

    proj_kernel<<<dim3(M_ / 64, 3), 256>>>(x, Wk, Wq, Wv);
    attn_kernel<<<dim3(S_ / BM, B_), 256, ATTN_SMEM>>>(out);
}

// round 7
// speedup vs baseline: 1.1123x; 1.1123x over previous
#include <cuda_runtime.h>

#define B_ 4
#define S_ 2048
#define E_ 1024
#define A_ 128
#define M_ (B_*S_)   // 8192

// scratch (device globals: no allocation allowed)
__device__ float g_q [M_*A_];        // [b][s][a], pre-scaled by 1/sqrt(A)
__device__ float g_kt[B_*A_*S_];     // [b][a][s]  (K transposed)
__device__ float g_v [M_*A_];        // [b][s][a]

// ---------------------------------------------------------------------------
// Projection: y[m][n] = sum_e x[m][e] * W[n][e]
// grid (128, 3): 3 -> which of K/Q/V. block 256 = 32c x 8r, micro 8 rows x 4 cols
// (measured ~92% of fp32 FFMA roofline -- unchanged this round)
// ---------------------------------------------------------------------------
#define KT 32

__global__ __launch_bounds__(256) void proj_kernel(
    const float* __restrict__ x,
    const float* __restrict__ Wk,
    const float* __restrict__ Wq,
    const float* __restrict__ Wv)
{
    const int which = blockIdx.y;               // 0=K, 1=Q, 2=V
    const float* __restrict__ W = (which == 0) ? Wk : ((which == 1) ? Wq : Wv);
    const int m0  = blockIdx.x * 64;
    const int tid = threadIdx.x;
    const int c   = tid & 31;
    const int r   = tid >> 5;

    __shared__ float xs[64 * 33];
    __shared__ float ws[128 * 33];

    float acc[8][4];
#pragma unroll
    for (int i = 0; i < 8; i++)
#pragma unroll
        for (int j = 0; j < 4; j++) acc[i][j] = 0.f;

    const int xrow = tid >> 2;            // 0..63
    const int xcb  = (tid & 3) * 8;       // 0,8,16,24
    const int wrow = tid >> 1;            // 0..127
    const int wcb  = (tid & 1) * 16;      // 0,16

    for (int kt = 0; kt < E_; kt += KT) {
        float4 xa = *(const float4*)&x[(m0 + xrow) * E_ + kt + xcb];
        float4 xb = *(const float4*)&x[(m0 + xrow) * E_ + kt + xcb + 4];
        float4 w0 = *(const float4*)&W[wrow * E_ + kt + wcb];
        float4 w1 = *(const float4*)&W[wrow * E_ + kt + wcb + 4];
        float4 w2 = *(const float4*)&W[wrow * E_ + kt + wcb + 8];
        float4 w3 = *(const float4*)&W[wrow * E_ + kt + wcb + 12];

        __syncthreads();
        {
            float* px = &xs[xrow * 33 + xcb];
            px[0]=xa.x; px[1]=xa.y; px[2]=xa.z; px[3]=xa.w;
            px[4]=xb.x; px[5]=xb.y; px[6]=xb.z; px[7]=xb.w;
            float* pw = &ws[wrow * 33 + wcb];
            pw[0]=w0.x; pw[1]=w0.y; pw[2]=w0.z; pw[3]=w0.w;
            pw[4]=w1.x; pw[5]=w1.y; pw[6]=w1.z; pw[7]=w1.w;
            pw[8]=w2.x; pw[9]=w2.y; pw[10]=w2.z; pw[11]=w2.w;
            pw[12]=w3.x; pw[13]=w3.y; pw[14]=w3.z; pw[15]=w3.w;
        }
        __syncthreads();

#pragma unroll 4
        for (int kk = 0; kk < KT; kk++) {
            float a[8];
#pragma unroll
            for (int i = 0; i < 8; i++) a[i] = xs[(r * 8 + i) * 33 + kk];
            float b0 = ws[(c      ) * 33 + kk];
            float b1 = ws[(c + 32 ) * 33 + kk];
            float b2 = ws[(c + 64 ) * 33 + kk];
            float b3 = ws[(c + 96 ) * 33 + kk];
#pragma unroll
            for (int i = 0; i < 8; i++) {
                acc[i][0] += a[i] * b0;
                acc[i][1] += a[i] * b1;
                acc[i][2] += a[i] * b2;
                acc[i][3] += a[i] * b3;
            }
        }
    }

    const float qscale = 0.08838834764831843f;  // 1/sqrt(128)
#pragma unroll
    for (int i = 0; i < 8; i++) {
        const int m = m0 + r * 8 + i;
#pragma unroll
        for (int j = 0; j < 4; j++) {
            const int n = c + 32 * j;
            float v = acc[i][j];
            if (which == 1) {
                g_q[m * A_ + n] = v * qscale;
            } else if (which == 2) {
                g_v[m * A_ + n] = v;
            } else {
                const int bb = m >> 11;          // /2048
                const int s  = m & (S_ - 1);
                g_kt[(bb * A_ + n) * S_ + s] = v;
            }
        }
    }
}

// ---------------------------------------------------------------------------
// Flash attention (causal), fp32, load-balanced.
// BM=32 queries/CTA -> 64 q-tiles/batch; grid (64, 4) = 256 CTAs launched
// LONGEST-FIRST (qt = 63 - bx) so wave-1 takes all long CTAs and wave-2
// work-stealing backfills with short ones. Makespan ~16 unit-tiles vs 32.
// block 256 = 32c x 8r; per-thread micro-tile 4 rows x 4 cols.
// ---------------------------------------------------------------------------
#define BM 32
#define BN 128
#define QP 132   // smem pitch (floats), 16B-aligned rows

// q_s[32][QP] + k_s[128][QP] + v_s[128][QP] + p_s[32][QP]
#define ATTN_SMEM ((32 + 128 + 128 + 32) * QP * 4)

__global__ __launch_bounds__(256, 1) void attn_kernel(float* __restrict__ out)
{
    extern __shared__ float sm[];
    float* q_s = sm;                    // [32][QP]   q_s[row][d]
    float* k_s = q_s + 32  * QP;        // [128][QP]  k_s[d][key]
    float* v_s = k_s + 128 * QP;        // [128][QP]  v_s[key][d]
    float* p_s = v_s + 128 * QP;        // [32][QP]   p_s[row][key]

    const int qt  = 63 - blockIdx.x;    // longest CTAs get lowest bids
    const int b   = blockIdx.y;         // 0..3
    const int q0  = qt * BM;
    const int tid = threadIdx.x;
    const int c   = tid & 31;
    const int r   = tid >> 5;

    // load Q tile (pre-scaled): 32 rows x 128 d
    {
        const int row = tid >> 3;              // 0..31
        const int cb  = (tid & 7) * 16;        // 0..112
        const float* gq = &g_q[(b * S_ + q0 + row) * A_ + cb];
        float* dq = &q_s[row * QP + cb];
#pragma unroll
        for (int u = 0; u < 4; u++)
            *(float4*)(dq + u * 4) = *(const float4*)(gq + u * 4);
    }

    float m_i[4], l_i[4], o[4][4];
#pragma unroll
    for (int i = 0; i < 4; i++) {
        m_i[i] = -1e30f; l_i[i] = 0.f;
#pragma unroll
        for (int j = 0; j < 4; j++) o[i][j] = 0.f;
    }

    const int hrow = tid >> 1;                 // 0..127
    const int hcb  = (tid & 1) * 64;           // 0,64
    const int ntiles = (qt >> 2) + 1;          // ceil((q0+BM)/BN)

    for (int t = 0; t < ntiles; t++) {
        const int kb = t * BN;

        __syncthreads();   // Q ready (t=0) / prev PV done
        {
            const float* gk = &g_kt[(b * A_ + hrow) * S_ + kb + hcb];
            float* dk = &k_s[hrow * QP + hcb];
#pragma unroll
            for (int u = 0; u < 16; u++)
                *(float4*)(dk + u * 4) = *(const float4*)(gk + u * 4);
            const float* gv = &g_v[(b * S_ + kb + hrow) * A_ + hcb];
            float* dv = &v_s[hrow * QP + hcb];
#pragma unroll
            for (int u = 0; u < 16; u++)
                *(float4*)(dv + u * 4) = *(const float4*)(gv + u * 4);
        }
        __syncthreads();

        // S = Q K^T (Q already scaled). A-operand as float4 per 4 k-steps.
        float sacc[4][4];
#pragma unroll
        for (int i = 0; i < 4; i++)
#pragma unroll
            for (int j = 0; j < 4; j++) sacc[i][j] = 0.f;

#pragma unroll 2
        for (int kk = 0; kk < 128; kk += 4) {
            float a[4][4];
#pragma unroll
            for (int i = 0; i < 4; i++) {
                float4 av = *(const float4*)&q_s[(r * 4 + i) * QP + kk];
                a[i][0] = av.x; a[i][1] = av.y; a[i][2] = av.z; a[i][3] = av.w;
            }
#pragma unroll
            for (int u = 0; u < 4; u++) {
                float4 bb = *(const float4*)&k_s[(kk + u) * QP + c * 4];
#pragma unroll
                for (int i = 0; i < 4; i++) {
                    sacc[i][0] += a[i][u] * bb.x;
                    sacc[i][1] += a[i][u] * bb.y;
                    sacc[i][2] += a[i][u] * bb.z;
                    sacc[i][3] += a[i][u] * bb.w;
                }
            }
        }

        // causal mask (only on the diagonal tile)
        if (kb + BN - 1 > q0) {
#pragma unroll
            for (int i = 0; i < 4; i++) {
                const int qg = q0 + r * 4 + i;
#pragma unroll
                for (int j = 0; j < 4; j++) {
                    const int kj = kb + c * 4 + j;
                    if (kj > qg) sacc[i][j] = -1e30f;
                }
            }
        }

        // online softmax (row = warp; shfl reductions)
#pragma unroll
        for (int i = 0; i < 4; i++) {
            float mx = fmaxf(fmaxf(sacc[i][0], sacc[i][1]),
                             fmaxf(sacc[i][2], sacc[i][3]));
#pragma unroll
            for (int off = 16; off > 0; off >>= 1)
                mx = fmaxf(mx, __shfl_xor_sync(0xffffffffu, mx, off));
            const float mnew  = fmaxf(m_i[i], mx);
            const float alpha = __expf(m_i[i] - mnew);
            float4 p;
            p.x = __expf(sacc[i][0] - mnew);
            p.y = __expf(sacc[i][1] - mnew);
            p.z = __expf(sacc[i][2] - mnew);
            p.w = __expf(sacc[i][3] - mnew);
            float ss = (p.x + p.y) + (p.z + p.w);
#pragma unroll
            for (int off = 16; off > 0; off >>= 1)
                ss += __shfl_xor_sync(0xffffffffu, ss, off);
            l_i[i] = l_i[i] * alpha + ss;
            m_i[i] = mnew;
            *(float4*)&p_s[(r * 4 + i) * QP + c * 4] = p;
#pragma unroll
            for (int j = 0; j < 4; j++) o[i][j] *= alpha;
        }
        __syncwarp();   // p_s rows are warp-private

        // O += P V   (P as float4 per 4 key-steps)
#pragma unroll 2
        for (int jj = 0; jj < 128; jj += 4) {
            float p[4][4];
#pragma unroll
            for (int i = 0; i < 4; i++) {
                float4 pv = *(const float4*)&p_s[(r * 4 + i) * QP + jj];
                p[i][0] = pv.x; p[i][1] = pv.y; p[i][2] = pv.z; p[i][3] = pv.w;
            }
#pragma unroll
            for (int u = 0; u < 4; u++) {
                float4 vv = *(const float4*)&v_s[(jj + u) * QP + c * 4];
#pragma unroll
                for (int i = 0; i < 4; i++) {
                    o[i][0] += p[i][u] * vv.x;
                    o[i][1] += p[i][u] * vv.y;
                    o[i][2] += p[i][u] * vv.z;
                    o[i][3] += p[i][u] * vv.w;
                }
            }
        }
    }

    // epilogue
#pragma unroll
    for (int i = 0; i < 4; i++) {
        const float inv = 1.f / l_i[i];
        float4 res;
        res.x = o[i][0] * inv;
        res.y = o[i][1] * inv;
        res.z = o[i][2] * inv;
        res.w = o[i][3] * inv;
        *(float4*)&out[(b * S_ + q0 + r * 4 + i) * A_ + c * 4] = res;
    }
}

// ---------------------------------------------------------------------------
extern "C" void kernel_launch(void* const* d_in, const int* in_sizes, int n_in,
                              void* d_out, int out_size)
{
    const float* x  = (const float*)d_in[0];   // embedded [4,2048,1024]
    const float* Wk = (const float*)d_in[1];   // [128,1024]
    const float* Wq = (const float*)d_in[2];
    const float* Wv = (const float*)d_in[3];
    float* out = (float*)d_out;                // [4,2048,128] fp32

    cudaFuncSetAttribute(attn_kernel,
                         cudaFuncAttributeMaxDynamicSharedMemorySize,
                         ATTN_SMEM);

    proj_kernel<<<dim3(M_ / 64, 3), 256>>>(x, Wk, Wq, Wv);
    attn_kernel<<<dim3(64, B_), 256, ATTN_SMEM>>>(out);
}